// round 7
// baseline (speedup 1.0000x reference)
#include <cuda_runtime.h>
#include <cuda_bf16.h>
#include <cstdint>

// Problem: x [16, 256, 128, 128] f32.
//  1) weight[b,c] = mean over H,W
//  2) idx[b,:] = argsort(weight[b]) ascending, take first 16 (stable)
//  3) out[b,k,:,:] = x[b, idx[b,k], :, :]
//
// R7: ONE kernel, grid = 4096 mean blocks + 1024 gather blocks appended at
// the tail. In-order CTA delivery means gather blocks only become resident
// as mean blocks retire — their batch's means are (almost always) already
// published, so they copy immediately, overlapped with the remaining mean
// blocks' DRAM stream. No kernel boundary, no gather launch ramp.
// Last-finisher block per batch (atomic ticket) does the stable bottom-16
// rank and sets a ready flag. __launch_bounds__(256,8) caps regs at 32.

#define B 16
#define C 256
#define HW 16384          // 128*128
#define K 16
#define MEAN_BLOCKS 4096
#define GATHER_BLOCKS 1024  // 4 per output plane (quarter planes)

__device__ float g_weight[B * C];
__device__ int   g_idx[B * K];
// g_sync[0..15] = per-batch completion counters, g_sync[16..31] = ready flags
__device__ int   g_sync[2 * B];

__global__ __launch_bounds__(256, 8) void fused_kernel(const float* __restrict__ x,
                                                       float* __restrict__ out) {
    const int bid = blockIdx.x;
    const int t   = threadIdx.x;

    if (bid < MEAN_BLOCKS) {
        // ================= Phase A: mean of plane bid =================
        const int b = bid >> 8;
        const float4* __restrict__ p =
            reinterpret_cast<const float4*>(x + (size_t)bid * HW);
        float s0 = 0.f, s1 = 0.f, s2 = 0.f, s3 = 0.f;
#pragma unroll
        for (int i = 0; i < 16; i += 4) {
            float4 v0 = __ldg(&p[t + (i + 0) * 256]);
            float4 v1 = __ldg(&p[t + (i + 1) * 256]);
            float4 v2 = __ldg(&p[t + (i + 2) * 256]);
            float4 v3 = __ldg(&p[t + (i + 3) * 256]);
            s0 += (v0.x + v0.y) + (v0.z + v0.w);
            s1 += (v1.x + v1.y) + (v1.z + v1.w);
            s2 += (v2.x + v2.y) + (v2.z + v2.w);
            s3 += (v3.x + v3.y) + (v3.z + v3.w);
        }
        float s = (s0 + s1) + (s2 + s3);
#pragma unroll
        for (int off = 16; off > 0; off >>= 1)
            s += __shfl_down_sync(0xFFFFFFFFu, s, off);

        __shared__ float sred[8];
        __shared__ int   s_last;
        if ((t & 31) == 0) sred[t >> 5] = s;
        __syncthreads();
        if (t < 8) {
            float v = sred[t];
#pragma unroll
            for (int off = 4; off > 0; off >>= 1)
                v += __shfl_down_sync(0xFFu, v, off);
            if (t == 0) {
                g_weight[bid] = v * (1.0f / (float)HW);
                __threadfence();                       // publish mean
                const int old = atomicAdd(&g_sync[b], 1);
                s_last = (old == C - 1);               // last finisher
            }
        }
        __syncthreads();
        if (!s_last) return;

        // ---- last block of batch b: stable bottom-16 select ----
        __threadfence();
        __shared__ float sw[C];
        sw[t] = __ldcg(&g_weight[b * C + t]);
        __syncthreads();

        const float v = sw[t];
        int rank = 0;
#pragma unroll 8
        for (int j = 0; j < C; ++j) {
            const float u = sw[j];
            rank += (u < v) || (u == v && j < t);
        }
        if (rank < K) g_idx[b * K + rank] = t;
        __syncthreads();
        if (t == 0) {
            __threadfence();                           // publish g_idx
            atomicExch(&g_sync[B + b], 1);             // ready flag
        }
        return;
    }

    // ================= Phase B: gather (tail of grid) =================
    const int g     = bid - MEAN_BLOCKS;               // 0..1023
    const int plane = g >> 2;                          // 0..255
    const int q     = g & 3;                           // quarter
    const int b     = plane >> 4;

    if (t == 0) {
        while (atomicAdd(&g_sync[B + b], 0) == 0) __nanosleep(64);
    }
    __syncthreads();                                   // acquire for whole block

    const int c = __ldcg(&g_idx[plane]);

    const float4* __restrict__ src = reinterpret_cast<const float4*>(
        x + ((size_t)b * C + c) * HW) + q * 1024;
    float4* __restrict__ dst = reinterpret_cast<float4*>(
        out + (size_t)plane * HW) + q * 1024;

    float4 w[4];
#pragma unroll
    for (int i = 0; i < 4; ++i)
        w[i] = __ldg(&src[t + i * 256]);               // 4 loads in flight
#pragma unroll
    for (int i = 0; i < 4; ++i)
        __stcs(&dst[t + i * 256], w[i]);               // streaming stores
}

// ---------------------------------------------------------------------------
extern "C" void kernel_launch(void* const* d_in, const int* in_sizes, int n_in,
                              void* d_out, int out_size) {
    const float* x = (const float*)d_in[0];
    float* out = (float*)d_out;

    void* sptr = nullptr;
    cudaGetSymbolAddress(&sptr, g_sync);
    cudaMemsetAsync(sptr, 0, 2 * B * sizeof(int));     // graph-capturable node

    fused_kernel<<<MEAN_BLOCKS + GATHER_BLOCKS, 256>>>(x, out);
}